// round 12
// baseline (speedup 1.0000x reference)
#include <cuda_runtime.h>

// out[i] = sum_j S[i][j] * w[j]   (S: [n,n] row-major fp32, w: [n] fp32)
// One CTA per row, 128 threads (vs the 256-thread baseline at 150.0us):
// same 64 warps/SM occupancy but 16 finer-grained CTAs/SM, so each row's
// tail reduction stalls only 4 warps and the distributor overlaps
// drain/launch at finer granularity. Same float4 loop body / traffic.
__global__ void __launch_bounds__(128) rowdot128_kernel(
    const float* __restrict__ S,
    const float* __restrict__ w,
    float* __restrict__ out,
    int n)
{
    const int row = blockIdx.x;
    const float4* __restrict__ s4 = reinterpret_cast<const float4*>(S + (size_t)row * n);
    const float4* __restrict__ w4 = reinterpret_cast<const float4*>(w);

    const int n4 = n >> 2;  // 4096 float4 per row -> 32 iterations/thread
    float acc = 0.0f;

    for (int i = threadIdx.x; i < n4; i += blockDim.x) {
        float4 a = s4[i];
        float4 b = w4[i];
        acc = fmaf(a.x, b.x, acc);
        acc = fmaf(a.y, b.y, acc);
        acc = fmaf(a.z, b.z, acc);
        acc = fmaf(a.w, b.w, acc);
    }

    // Warp reduce
    #pragma unroll
    for (int off = 16; off > 0; off >>= 1)
        acc += __shfl_down_sync(0xFFFFFFFFu, acc, off);

    // Block reduce across 4 warps
    __shared__ float warp_sums[4];
    const int lane = threadIdx.x & 31;
    const int wid  = threadIdx.x >> 5;
    if (lane == 0) warp_sums[wid] = acc;
    __syncthreads();

    if (wid == 0) {
        float v = (lane < 4) ? warp_sums[lane] : 0.0f;
        #pragma unroll
        for (int off = 2; off > 0; off >>= 1)
            v += __shfl_down_sync(0xFFFFFFFFu, v, off);
        if (lane == 0) out[row] = v;
    }
}

extern "C" void kernel_launch(void* const* d_in, const int* in_sizes, int n_in,
                              void* d_out, int out_size) {
    const float* S = (const float*)d_in[0];
    const float* w = (const float*)d_in[1];
    float* out = (float*)d_out;

    const int n = in_sizes[1];  // N = 16384

    rowdot128_kernel<<<n, 128>>>(S, w, out, n);
}

// round 13
// speedup vs baseline: 1.0294x; 1.0294x over previous
#include <cuda_runtime.h>

// out[i] = sum_j S[i][j] * w[j]
// One CTA per row. 256 threads, float4 loads, warp-shuffle reduction.
// FINAL: best-measured variant (150.0-151.6us across 4 runs, 7.13-7.15
// TB/s = ~89-90% of HBM spec; traffic floor at that rate is ~150.3us ->
// at the memory wall). The blockDim.x loop stride and bare
// __launch_bounds__(256) are intentional: they produce the ptxas unroll
// that front-batches LDG.128 (high MLP_p1). Measured-worse alternatives:
// persistence (-10%), v8 loads (-1.6%), __ldcs (-5%), 2-row blocking
// (tie), literal-stride + min-blocks codegen (-4%), 128-thread blocks
// (-1.5%).
__global__ void __launch_bounds__(256) rowdot_kernel(
    const float* __restrict__ S,
    const float* __restrict__ w,
    float* __restrict__ out,
    int n)
{
    const int row = blockIdx.x;
    const float4* __restrict__ s4 = reinterpret_cast<const float4*>(S + (size_t)row * n);
    const float4* __restrict__ w4 = reinterpret_cast<const float4*>(w);

    const int n4 = n >> 2;  // n/4 float4 elements per row
    float acc = 0.0f;

    // Coalesced grid of float4 loads; 16 iterations/thread at n=16384, bd=256.
    for (int i = threadIdx.x; i < n4; i += blockDim.x) {
        float4 a = s4[i];
        float4 b = w4[i];
        acc = fmaf(a.x, b.x, acc);
        acc = fmaf(a.y, b.y, acc);
        acc = fmaf(a.z, b.z, acc);
        acc = fmaf(a.w, b.w, acc);
    }

    // Warp reduce
    #pragma unroll
    for (int off = 16; off > 0; off >>= 1)
        acc += __shfl_down_sync(0xFFFFFFFFu, acc, off);

    // Block reduce across 8 warps
    __shared__ float warp_sums[8];
    const int lane = threadIdx.x & 31;
    const int wid  = threadIdx.x >> 5;
    if (lane == 0) warp_sums[wid] = acc;
    __syncthreads();

    if (wid == 0) {
        float v = (lane < 8) ? warp_sums[lane] : 0.0f;
        #pragma unroll
        for (int off = 4; off > 0; off >>= 1)
            v += __shfl_down_sync(0xFFFFFFFFu, v, off);
        if (lane == 0) out[row] = v;
    }
}

extern "C" void kernel_launch(void* const* d_in, const int* in_sizes, int n_in,
                              void* d_out, int out_size) {
    const float* S = (const float*)d_in[0];
    const float* w = (const float*)d_in[1];
    float* out = (float*)d_out;

    const int n = in_sizes[1];  // weights length = N = 16384

    rowdot_kernel<<<n, 256>>>(S, w, out, n);
}